// round 13
// baseline (speedup 1.0000x reference)
#include <cuda_runtime.h>
#include <math.h>

#define TINYF 1.17549435e-38f

// ---------------- scratch (static device, allocation-free) ----------------
__device__ float g_last[512 * 128];
__device__ float g_hph[60 * 512 * 128];
__device__ float g_hphn[60 * 512];
__device__ float g_cmax, g_brange;
__constant__ float DECAY[6] = {1.0f, 0.9f, 0.81f, 0.729f, 0.6561f, 0.59049f};

// ---------------- compile-time threefry2x32 (JAX algorithm) ----------------
struct KP { unsigned a, b; };
constexpr unsigned rotlc(unsigned x, int r) { return (x << r) | (x >> (32 - r)); }
constexpr KP tfc(unsigned k0, unsigned k1, unsigned c0, unsigned c1) {
    unsigned ks[3] = { k0, k1, k0 ^ k1 ^ 0x1BD11BDAu };
    unsigned x0 = c0 + k0, x1 = c1 + k1;
    const int RA[4] = {13, 15, 26, 6}, RB[4] = {17, 29, 16, 24};
    for (int g = 0; g < 5; ++g) {
        for (int i = 0; i < 4; ++i) {
            int r = (g & 1) ? RB[i] : RA[i];
            x0 += x1; x1 = rotlc(x1, r); x1 ^= x0;
        }
        x0 += ks[(g + 1) % 3];
        x1 += ks[(g + 2) % 3] + (unsigned)(g + 1);
    }
    return { x0, x1 };
}
// key(42) = (0,42); split -> children at 64-bit counters 0 and 1 (partitionable)
constexpr KP KN = tfc(0u, 42u, 0u, 0u);  // knoise
constexpr KP KS = tfc(0u, 42u, 0u, 1u);  // ksample

// folded 32-bit draw at counter (0, c1): x0 ^ x1
template<unsigned K0, unsigned K1>
__device__ __forceinline__ unsigned tf_fold(unsigned c1) {
    constexpr unsigned K2 = K0 ^ K1 ^ 0x1BD11BDAu;
    unsigned x0 = K0, x1 = c1 + K1;
#define TFR(r) { x0 += x1; x1 = __funnelshift_l(x1, x1, r); x1 ^= x0; }
    TFR(13) TFR(15) TFR(26) TFR(6)   x0 += K1; x1 += K2 + 1u;
    TFR(17) TFR(29) TFR(16) TFR(24)  x0 += K2; x1 += K0 + 2u;
    TFR(13) TFR(15) TFR(26) TFR(6)   x0 += K0; x1 += K1 + 3u;
    TFR(17) TFR(29) TFR(16) TFR(24)  x0 += K1; x1 += K2 + 4u;
    TFR(13) TFR(15) TFR(26) TFR(6)   x0 += K2; x1 += K0 + 5u;
#undef TFR
    return x0 ^ x1;
}

// ---------------- XLA ErfInv (Giles), double log1p for fast-math safety ----
__device__ __forceinline__ float erfinv_f(float x) {
    float xx = __fmul_rn(x, x);
    float w = (float)(-log1p(-(double)xx));
    float p;
    if (w < 5.0f) {
        w = w - 2.5f;
        p = 2.81022636e-08f;
        p = fmaf(p, w, 3.43273939e-07f);
        p = fmaf(p, w, -3.5233877e-06f);
        p = fmaf(p, w, -4.39150654e-06f);
        p = fmaf(p, w, 0.00021858087f);
        p = fmaf(p, w, -0.00125372503f);
        p = fmaf(p, w, -0.00417768164f);
        p = fmaf(p, w, 0.246640727f);
        p = fmaf(p, w, 1.50140941f);
    } else {
        w = (float)sqrt((double)w) - 3.0f;
        p = -0.000200214257f;
        p = fmaf(p, w, 0.000100950558f);
        p = fmaf(p, w, 0.00134934322f);
        p = fmaf(p, w, -0.00367342844f);
        p = fmaf(p, w, 0.00573950773f);
        p = fmaf(p, w, -0.0076224613f);
        p = fmaf(p, w, 0.00943887047f);
        p = fmaf(p, w, 1.00167406f);
        p = fmaf(p, w, 2.83297682f);
    }
    return __fmul_rn(p, x);
}

__device__ __forceinline__ float sigm(float v) { return 1.0f / (1.0f + expf(-v)); }

// ================= Kernel A: GRU x2 + traj/conf heads (per batch row) ======
__global__ __launch_bounds__(128) void k_head(
    const float* __restrict__ x, const float* __restrict__ hidden,
    const float* __restrict__ wih0, const float* __restrict__ whh0,
    const float* __restrict__ bih0, const float* __restrict__ bhh0,
    const float* __restrict__ wih1, const float* __restrict__ whh1,
    const float* __restrict__ bih1, const float* __restrict__ bhh1,
    const float* __restrict__ hgw1, const float* __restrict__ hgb1,
    const float* __restrict__ hgw2, const float* __restrict__ hgb2,
    const float* __restrict__ hgw3, const float* __restrict__ hgb3,
    const float* __restrict__ cfw1, const float* __restrict__ cfb1,
    const float* __restrict__ cfw2, const float* __restrict__ cfb2,
    float* __restrict__ out)
{
    const int b = blockIdx.x, h = threadIdx.x;
    __shared__ float sm0[128], sm1[128], sm2[128], sm3[128];
    sm0[h] = hidden[b * 128 + h];
    sm1[h] = hidden[65536 + b * 128 + h];
    __syncthreads();
    const float xa = x[2 * b], xb = x[2 * b + 1];
    // ---- layer 0 ----
    float ar = 0.f, az = 0.f, an = 0.f;
#pragma unroll 8
    for (int k = 0; k < 128; ++k) {
        float hv = sm0[k];
        ar = fmaf(hv, whh0[h * 128 + k], ar);
        az = fmaf(hv, whh0[(128 + h) * 128 + k], az);
        an = fmaf(hv, whh0[(256 + h) * 128 + k], an);
    }
    float gir = (xa * wih0[2 * h] + xb * wih0[2 * h + 1]) + bih0[h];
    float giz = (xa * wih0[2 * (128 + h)] + xb * wih0[2 * (128 + h) + 1]) + bih0[128 + h];
    float gin = (xa * wih0[2 * (256 + h)] + xb * wih0[2 * (256 + h) + 1]) + bih0[256 + h];
    float ghr = ar + bhh0[h], ghz = az + bhh0[128 + h], ghn = an + bhh0[256 + h];
    float r = sigm(gir + ghr), z = sigm(giz + ghz);
    float n = tanhf(gin + r * ghn);
    float h0v = (1.0f - z) * n + z * sm0[h];
    __syncthreads();
    sm2[h] = h0v;
    __syncthreads();
    // ---- layer 1 ----
    float ir = 0.f, iz = 0.f, inn = 0.f, hr = 0.f, hz = 0.f, hn = 0.f;
#pragma unroll 8
    for (int k = 0; k < 128; ++k) {
        float av = sm2[k], bv = sm1[k];
        ir  = fmaf(av, wih1[h * 128 + k], ir);
        iz  = fmaf(av, wih1[(128 + h) * 128 + k], iz);
        inn = fmaf(av, wih1[(256 + h) * 128 + k], inn);
        hr  = fmaf(bv, whh1[h * 128 + k], hr);
        hz  = fmaf(bv, whh1[(128 + h) * 128 + k], hz);
        hn  = fmaf(bv, whh1[(256 + h) * 128 + k], hn);
    }
    gir = ir + bih1[h]; giz = iz + bih1[128 + h]; gin = inn + bih1[256 + h];
    ghr = hr + bhh1[h]; ghz = hz + bhh1[128 + h]; ghn = hn + bhh1[256 + h];
    r = sigm(gir + ghr); z = sigm(giz + ghz);
    n = tanhf(gin + r * ghn);
    float lastv = (1.0f - z) * n + z * sm1[h];
    g_last[b * 128 + h] = lastv;
    __syncthreads();
    sm3[h] = lastv;
    __syncthreads();
    // ---- hg head ----
    float a1 = 0.f;
#pragma unroll 8
    for (int k = 0; k < 128; ++k) a1 = fmaf(sm3[k], hgw1[h * 128 + k], a1);
    sm0[h] = fmaxf(a1 + hgb1[h], 0.f);
    __syncthreads();
    if (h < 64) {
        float a2 = 0.f;
#pragma unroll 8
        for (int k = 0; k < 128; ++k) a2 = fmaf(sm0[k], hgw2[h * 128 + k], a2);
        sm1[h] = fmaxf(a2 + hgb2[h], 0.f);
    }
    __syncthreads();
    if (h < 120) {
        float a3 = 0.f;
#pragma unroll 8
        for (int k = 0; k < 64; ++k) a3 = fmaf(sm1[k], hgw3[h * 64 + k], a3);
        out[b * 720 + h] = a3 + hgb3[h];
    }
    // ---- cf head ----
    if (h < 64) {
        float c1 = 0.f;
#pragma unroll 8
        for (int k = 0; k < 128; ++k) c1 = fmaf(sm3[k], cfw1[h * 128 + k], c1);
        sm2[h] = fmaxf(c1 + cfb1[h], 0.f);
    }
    __syncthreads();
    if (h < 60) {
        float cc = 0.f;
#pragma unroll 8
        for (int k = 0; k < 64; ++k) cc = fmaf(sm2[k], cfw2[h * 64 + k], cc);
        sm0[h] = cc + cfb2[h];
    }
    __syncthreads();
    if (h == 0) {
        float ssum = 0.f;
        for (int j = 0; j < 60; ++j) ssum += sm0[j];
        sm0[64] = ssum / 60.0f;
    }
    __syncthreads();
    if (h < 6) out[368640 + b * 6 + h] = sm0[64] * DECAY[h];
}

// ============ Kernel W: max ||hp_w2 row||, range(hp_b2) ====================
__global__ void k_w2(const float* __restrict__ w2, const float* __restrict__ b2) {
    __shared__ float sc[512], sx[512], sn[512];
    int tid = threadIdx.x;
    float cm = 0.f, bmx = -1e30f, bmn = 1e30f;
    for (int rr = tid; rr < 4096; rr += 512) {
        const float* w = w2 + rr * 128;
        float s = 0.f;
#pragma unroll 8
        for (int k = 0; k < 128; ++k) s = fmaf(w[k], w[k], s);
        cm = fmaxf(cm, s);
        float bv = b2[rr];
        bmx = fmaxf(bmx, bv); bmn = fminf(bmn, bv);
    }
    sc[tid] = cm; sx[tid] = bmx; sn[tid] = bmn;
    __syncthreads();
    for (int s2 = 256; s2 > 0; s2 >>= 1) {
        if (tid < s2) {
            sc[tid] = fmaxf(sc[tid], sc[tid + s2]);
            sx[tid] = fmaxf(sx[tid], sx[tid + s2]);
            sn[tid] = fminf(sn[tid], sn[tid + s2]);
        }
        __syncthreads();
    }
    if (tid == 0) { g_cmax = sqrtf(sc[0]); g_brange = sx[0] - sn[0]; }
}

// ============ Kernel B: normals -> noisy -> hph = relu(noisy@W1+b1) ========
__global__ __launch_bounds__(128) void k_hph(const float* __restrict__ hpw1,
                                             const float* __restrict__ hpb1) {
    int tb = blockIdx.x;           // t*512 + b
    int t = tb >> 9;
    int h = threadIdx.x;
    __shared__ float sn[128], sr[128];
    unsigned bits = tf_fold<KN.a, KN.b>((unsigned)(tb * 128 + h));
    float u01 = __uint_as_float(0x3f800000u | (bits >> 9)) - 1.0f;
    const float LO = __uint_as_float(0xBF7FFFFFu);   // nextafter(-1,0)
    float u = __fadd_rn(__fmul_rn(u01, 2.0f), LO);   // span rounds to exactly 2.0f
    u = fmaxf(LO, u);
    float nv = __fmul_rn(1.4142135623730951f, erfinv_f(u));
    float scale = __fmul_rn(0.1f, __fdiv_rn((float)t, 60.0f));
    float lastv = g_last[(tb & 511) * 128 + h];
    sn[h] = __fadd_rn(lastv, __fmul_rn(nv, scale));
    __syncthreads();
    float acc = 0.f;
#pragma unroll 16
    for (int k = 0; k < 128; ++k) acc = fmaf(sn[k], hpw1[h * 128 + k], acc);
    float v = fmaxf(acc + hpb1[h], 0.f);
    g_hph[tb * 128 + h] = v;
    sr[h] = v * v;
    __syncthreads();
    for (int s2 = 64; s2 > 0; s2 >>= 1) {
        if (h < s2) sr[h] += sr[h + s2];
        __syncthreads();
    }
    if (h == 0) g_hphn[tb] = sqrtf(sr[0]);
}

// ============ Kernel C: categorical via mantissa-argmax + candidate dots ===
__global__ __launch_bounds__(256) void k_samp(const float* __restrict__ w2,
                                              const float* __restrict__ b2,
                                              float* __restrict__ out) {
    __shared__ unsigned sm[4096];
    __shared__ __align__(16) float shph[128];
    __shared__ float rs[256];
    __shared__ int ri[256];
    __shared__ unsigned s_mth, s_wm[8];
    int row = blockIdx.x;                 // ((s*60)+t)*512 + b
    int b = row & 511;
    int q = row >> 9;
    int t = q % 60, s = q / 60;
    int tid = threadIdx.x;
    if (tid < 128) shph[tid] = g_hph[(t * 512 + b) * 128 + tid];
    unsigned base = (unsigned)row << 12;  // row*4096, fits u32
    unsigned mymax = 0;
#pragma unroll 4
    for (int i = tid; i < 4096; i += 256) {
        unsigned m = tf_fold<KS.a, KS.b>(base + (unsigned)i) >> 9;
        sm[i] = m;
        mymax = max(mymax, m);
    }
    unsigned wm = __reduce_max_sync(0xffffffffu, mymax);
    if ((tid & 31) == 0) s_wm[tid >> 5] = wm;
    __syncthreads();
    if (tid == 0) {
        unsigned M = s_wm[0];
#pragma unroll
        for (int j = 1; j < 8; ++j) M = max(M, s_wm[j]);
        double U = (double)(__uint_as_float(0x3f800000u | M) - 1.0f) + 1.17549435e-38;
        double gM = -log(-log(U));
        double delta = 2.0 * (double)g_hphn[t * 512 + b] * (double)g_cmax
                     + (double)g_brange + 0.05 + 1e-3 * fabs(gM);
        double uth = exp(-exp(-(gM - delta)));
        long mth = (long)floor(uth * 8388608.0) - 2;
        if (!(mth > 0) || !isfinite(uth)) mth = 0;
        s_mth = (unsigned)mth;
    }
    __syncthreads();
    unsigned mth = s_mth;
    float best = -1e30f;
    int bi = 2147483647;
    for (int i = tid; i < 4096; i += 256) {
        unsigned m = sm[i];
        if (m >= mth) {
            float u01 = __uint_as_float(0x3f800000u | m) - 1.0f;
            float U = __fadd_rn(u01, TINYF);
            float l1 = (float)log((double)U);          // f32-accurate, fast-math-proof
            float g = -(float)log((double)(-l1));
            const float4* wv = (const float4*)(w2 + i * 128);
            float acc = 0.f;
#pragma unroll
            for (int k = 0; k < 32; ++k) {
                float4 a = ((const float4*)shph)[k];
                float4 c = wv[k];
                acc = fmaf(a.x, c.x, acc); acc = fmaf(a.y, c.y, acc);
                acc = fmaf(a.z, c.z, acc); acc = fmaf(a.w, c.w, acc);
            }
            float score = __fadd_rn(g, acc + b2[i]);
            if (score > best) { best = score; bi = i; }   // first-index tie-break
        }
    }
    rs[tid] = best; ri[tid] = bi;
    __syncthreads();
    for (int s2 = 128; s2 > 0; s2 >>= 1) {
        if (tid < s2) {
            float o = rs[tid + s2]; int oi = ri[tid + s2];
            if (o > rs[tid] || (o == rs[tid] && oi < ri[tid])) { rs[tid] = o; ri[tid] = oi; }
        }
        __syncthreads();
    }
    if (tid == 0) {
        int idx = ri[0];
        float px = -50.0f + (float)(idx & 63) * 1.5625f + 0.78125f;
        float py = -50.0f + (float)(idx >> 6) * 1.5625f + 0.78125f;
        int o = b * 720 + (1 + s) * 120 + t * 2;
        out[o] = px;
        out[o + 1] = py;
    }
}

// =========================== launch ========================================
extern "C" void kernel_launch(void* const* d_in, const int* in_sizes, int n_in,
                              void* d_out, int out_size) {
    const float* x    = (const float*)d_in[0];
    const float* hid  = (const float*)d_in[1];
    const float* wih0 = (const float*)d_in[3];
    const float* whh0 = (const float*)d_in[4];
    const float* bih0 = (const float*)d_in[5];
    const float* bhh0 = (const float*)d_in[6];
    const float* wih1 = (const float*)d_in[7];
    const float* whh1 = (const float*)d_in[8];
    const float* bih1 = (const float*)d_in[9];
    const float* bhh1 = (const float*)d_in[10];
    const float* hgw1 = (const float*)d_in[11];
    const float* hgb1 = (const float*)d_in[12];
    const float* hgw2 = (const float*)d_in[13];
    const float* hgb2 = (const float*)d_in[14];
    const float* hgw3 = (const float*)d_in[15];
    const float* hgb3 = (const float*)d_in[16];
    const float* cfw1 = (const float*)d_in[17];
    const float* cfb1 = (const float*)d_in[18];
    const float* cfw2 = (const float*)d_in[19];
    const float* cfb2 = (const float*)d_in[20];
    const float* hpw1 = (const float*)d_in[21];
    const float* hpb1 = (const float*)d_in[22];
    const float* hpw2 = (const float*)d_in[23];
    const float* hpb2 = (const float*)d_in[24];
    float* out = (float*)d_out;

    k_head<<<512, 128>>>(x, hid, wih0, whh0, bih0, bhh0, wih1, whh1, bih1, bhh1,
                         hgw1, hgb1, hgw2, hgb2, hgw3, hgb3,
                         cfw1, cfb1, cfw2, cfb2, out);
    k_w2<<<1, 512>>>(hpw2, hpb2);
    k_hph<<<60 * 512, 128>>>(hpw1, hpb1);
    k_samp<<<5 * 60 * 512, 256>>>(hpw2, hpb2, out);
}

// round 14
// speedup vs baseline: 6.6269x; 6.6269x over previous
#include <cuda_runtime.h>
#include <math.h>

#define TINYF 1.17549435e-38f

extern "C" __device__ float __nv_log1pf(float);

// ---------------- scratch (static device, allocation-free) ----------------
__device__ float g_last[512 * 128];
__device__ float g_hph[60 * 512 * 128];
__device__ float g_hphn[60 * 512];
__device__ float g_cmax, g_brange;
__constant__ float DECAY[6] = {1.0f, 0.9f, 0.81f, 0.729f, 0.6561f, 0.59049f};

// ---------------- compile-time threefry2x32 (JAX algorithm) ----------------
struct KP { unsigned a, b; };
constexpr unsigned rotlc(unsigned x, int r) { return (x << r) | (x >> (32 - r)); }
constexpr KP tfc(unsigned k0, unsigned k1, unsigned c0, unsigned c1) {
    unsigned ks[3] = { k0, k1, k0 ^ k1 ^ 0x1BD11BDAu };
    unsigned x0 = c0 + k0, x1 = c1 + k1;
    const int RA[4] = {13, 15, 26, 6}, RB[4] = {17, 29, 16, 24};
    for (int g = 0; g < 5; ++g) {
        for (int i = 0; i < 4; ++i) {
            int r = (g & 1) ? RB[i] : RA[i];
            x0 += x1; x1 = rotlc(x1, r); x1 ^= x0;
        }
        x0 += ks[(g + 1) % 3];
        x1 += ks[(g + 2) % 3] + (unsigned)(g + 1);
    }
    return { x0, x1 };
}
// key(42) = (0,42); split -> children at 64-bit counters 0 and 1 (partitionable)
constexpr KP KN = tfc(0u, 42u, 0u, 0u);  // knoise
constexpr KP KS = tfc(0u, 42u, 0u, 1u);  // ksample

// folded 32-bit draw at counter (0, c1): x0 ^ x1
template<unsigned K0, unsigned K1>
__device__ __forceinline__ unsigned tf_fold(unsigned c1) {
    constexpr unsigned K2 = K0 ^ K1 ^ 0x1BD11BDAu;
    unsigned x0 = K0, x1 = c1 + K1;
#define TFR(r) { x0 += x1; x1 = __funnelshift_l(x1, x1, r); x1 ^= x0; }
    TFR(13) TFR(15) TFR(26) TFR(6)   x0 += K1; x1 += K2 + 1u;
    TFR(17) TFR(29) TFR(16) TFR(24)  x0 += K2; x1 += K0 + 2u;
    TFR(13) TFR(15) TFR(26) TFR(6)   x0 += K0; x1 += K1 + 3u;
    TFR(17) TFR(29) TFR(16) TFR(24)  x0 += K1; x1 += K2 + 4u;
    TFR(13) TFR(15) TFR(26) TFR(6)   x0 += K2; x1 += K0 + 5u;
#undef TFR
    return x0 ^ x1;
}

// ---------------- XLA ErfInv (Giles), all-float (libdevice log1p) ----------
__device__ __forceinline__ float erfinv_f(float x) {
    float xx = __fmul_rn(x, x);
    float w = -__nv_log1pf(-xx);
    float p;
    if (w < 5.0f) {
        w = w - 2.5f;
        p = 2.81022636e-08f;
        p = fmaf(p, w, 3.43273939e-07f);
        p = fmaf(p, w, -3.5233877e-06f);
        p = fmaf(p, w, -4.39150654e-06f);
        p = fmaf(p, w, 0.00021858087f);
        p = fmaf(p, w, -0.00125372503f);
        p = fmaf(p, w, -0.00417768164f);
        p = fmaf(p, w, 0.246640727f);
        p = fmaf(p, w, 1.50140941f);
    } else {
        w = __fsqrt_rn(w) - 3.0f;
        p = -0.000200214257f;
        p = fmaf(p, w, 0.000100950558f);
        p = fmaf(p, w, 0.00134934322f);
        p = fmaf(p, w, -0.00367342844f);
        p = fmaf(p, w, 0.00573950773f);
        p = fmaf(p, w, -0.0076224613f);
        p = fmaf(p, w, 0.00943887047f);
        p = fmaf(p, w, 1.00167406f);
        p = fmaf(p, w, 2.83297682f);
    }
    return __fmul_rn(p, x);
}

__device__ __forceinline__ float sigm(float v) { return 1.0f / (1.0f + expf(-v)); }

// ================= Kernel A: GRU x2 + traj/conf heads (per batch row) ======
__global__ __launch_bounds__(128) void k_head(
    const float* __restrict__ x, const float* __restrict__ hidden,
    const float* __restrict__ wih0, const float* __restrict__ whh0,
    const float* __restrict__ bih0, const float* __restrict__ bhh0,
    const float* __restrict__ wih1, const float* __restrict__ whh1,
    const float* __restrict__ bih1, const float* __restrict__ bhh1,
    const float* __restrict__ hgw1, const float* __restrict__ hgb1,
    const float* __restrict__ hgw2, const float* __restrict__ hgb2,
    const float* __restrict__ hgw3, const float* __restrict__ hgb3,
    const float* __restrict__ cfw1, const float* __restrict__ cfb1,
    const float* __restrict__ cfw2, const float* __restrict__ cfb2,
    float* __restrict__ out)
{
    const int b = blockIdx.x, h = threadIdx.x;
    __shared__ float sm0[128], sm1[128], sm2[128], sm3[128];
    sm0[h] = hidden[b * 128 + h];
    sm1[h] = hidden[65536 + b * 128 + h];
    __syncthreads();
    const float xa = x[2 * b], xb = x[2 * b + 1];
    // ---- layer 0 ----
    float ar = 0.f, az = 0.f, an = 0.f;
#pragma unroll 8
    for (int k = 0; k < 128; ++k) {
        float hv = sm0[k];
        ar = fmaf(hv, whh0[h * 128 + k], ar);
        az = fmaf(hv, whh0[(128 + h) * 128 + k], az);
        an = fmaf(hv, whh0[(256 + h) * 128 + k], an);
    }
    float gir = (xa * wih0[2 * h] + xb * wih0[2 * h + 1]) + bih0[h];
    float giz = (xa * wih0[2 * (128 + h)] + xb * wih0[2 * (128 + h) + 1]) + bih0[128 + h];
    float gin = (xa * wih0[2 * (256 + h)] + xb * wih0[2 * (256 + h) + 1]) + bih0[256 + h];
    float ghr = ar + bhh0[h], ghz = az + bhh0[128 + h], ghn = an + bhh0[256 + h];
    float r = sigm(gir + ghr), z = sigm(giz + ghz);
    float n = tanhf(gin + r * ghn);
    float h0v = (1.0f - z) * n + z * sm0[h];
    __syncthreads();
    sm2[h] = h0v;
    __syncthreads();
    // ---- layer 1 ----
    float ir = 0.f, iz = 0.f, inn = 0.f, hr = 0.f, hz = 0.f, hn = 0.f;
#pragma unroll 8
    for (int k = 0; k < 128; ++k) {
        float av = sm2[k], bv = sm1[k];
        ir  = fmaf(av, wih1[h * 128 + k], ir);
        iz  = fmaf(av, wih1[(128 + h) * 128 + k], iz);
        inn = fmaf(av, wih1[(256 + h) * 128 + k], inn);
        hr  = fmaf(bv, whh1[h * 128 + k], hr);
        hz  = fmaf(bv, whh1[(128 + h) * 128 + k], hz);
        hn  = fmaf(bv, whh1[(256 + h) * 128 + k], hn);
    }
    gir = ir + bih1[h]; giz = iz + bih1[128 + h]; gin = inn + bih1[256 + h];
    ghr = hr + bhh1[h]; ghz = hz + bhh1[128 + h]; ghn = hn + bhh1[256 + h];
    r = sigm(gir + ghr); z = sigm(giz + ghz);
    n = tanhf(gin + r * ghn);
    float lastv = (1.0f - z) * n + z * sm1[h];
    g_last[b * 128 + h] = lastv;
    __syncthreads();
    sm3[h] = lastv;
    __syncthreads();
    // ---- hg head ----
    float a1 = 0.f;
#pragma unroll 8
    for (int k = 0; k < 128; ++k) a1 = fmaf(sm3[k], hgw1[h * 128 + k], a1);
    sm0[h] = fmaxf(a1 + hgb1[h], 0.f);
    __syncthreads();
    if (h < 64) {
        float a2 = 0.f;
#pragma unroll 8
        for (int k = 0; k < 128; ++k) a2 = fmaf(sm0[k], hgw2[h * 128 + k], a2);
        sm1[h] = fmaxf(a2 + hgb2[h], 0.f);
    }
    __syncthreads();
    if (h < 120) {
        float a3 = 0.f;
#pragma unroll 8
        for (int k = 0; k < 64; ++k) a3 = fmaf(sm1[k], hgw3[h * 64 + k], a3);
        out[b * 720 + h] = a3 + hgb3[h];
    }
    // ---- cf head ----
    if (h < 64) {
        float c1 = 0.f;
#pragma unroll 8
        for (int k = 0; k < 128; ++k) c1 = fmaf(sm3[k], cfw1[h * 128 + k], c1);
        sm2[h] = fmaxf(c1 + cfb1[h], 0.f);
    }
    __syncthreads();
    if (h < 60) {
        float cc = 0.f;
#pragma unroll 8
        for (int k = 0; k < 64; ++k) cc = fmaf(sm2[k], cfw2[h * 64 + k], cc);
        sm0[h] = cc + cfb2[h];
    }
    __syncthreads();
    if (h == 0) {
        float ssum = 0.f;
        for (int j = 0; j < 60; ++j) ssum += sm0[j];
        sm0[64] = ssum / 60.0f;
    }
    __syncthreads();
    if (h < 6) out[368640 + b * 6 + h] = sm0[64] * DECAY[h];
}

// ============ Kernel W: max ||hp_w2 row||, range(hp_b2) ====================
__global__ void k_w2(const float* __restrict__ w2, const float* __restrict__ b2) {
    __shared__ float sc[512], sx[512], sn[512];
    int tid = threadIdx.x;
    float cm = 0.f, bmx = -1e30f, bmn = 1e30f;
    for (int rr = tid; rr < 4096; rr += 512) {
        const float* w = w2 + rr * 128;
        float s = 0.f;
#pragma unroll 8
        for (int k = 0; k < 128; ++k) s = fmaf(w[k], w[k], s);
        cm = fmaxf(cm, s);
        float bv = b2[rr];
        bmx = fmaxf(bmx, bv); bmn = fminf(bmn, bv);
    }
    sc[tid] = cm; sx[tid] = bmx; sn[tid] = bmn;
    __syncthreads();
    for (int s2 = 256; s2 > 0; s2 >>= 1) {
        if (tid < s2) {
            sc[tid] = fmaxf(sc[tid], sc[tid + s2]);
            sx[tid] = fmaxf(sx[tid], sx[tid + s2]);
            sn[tid] = fminf(sn[tid], sn[tid + s2]);
        }
        __syncthreads();
    }
    if (tid == 0) { g_cmax = sqrtf(sc[0]); g_brange = sx[0] - sn[0]; }
}

// ============ Kernel B: normals -> noisy -> hph = relu(noisy@W1+b1) ========
__global__ __launch_bounds__(128) void k_hph(const float* __restrict__ hpw1,
                                             const float* __restrict__ hpb1) {
    int tb = blockIdx.x;           // t*512 + b
    int t = tb >> 9;
    int h = threadIdx.x;
    __shared__ float sn[128], sr[128];
    unsigned bits = tf_fold<KN.a, KN.b>((unsigned)(tb * 128 + h));
    float u01 = __uint_as_float(0x3f800000u | (bits >> 9)) - 1.0f;
    const float LO = __uint_as_float(0xBF7FFFFFu);   // nextafter(-1,0)
    float u = __fadd_rn(__fmul_rn(u01, 2.0f), LO);   // span rounds to exactly 2.0f
    u = fmaxf(LO, u);
    float nv = __fmul_rn(1.4142135623730951f, erfinv_f(u));
    float scale = __fmul_rn(0.1f, __fdiv_rn((float)t, 60.0f));
    float lastv = g_last[(tb & 511) * 128 + h];
    sn[h] = __fadd_rn(lastv, __fmul_rn(nv, scale));
    __syncthreads();
    float acc = 0.f;
#pragma unroll 16
    for (int k = 0; k < 128; ++k) acc = fmaf(sn[k], hpw1[h * 128 + k], acc);
    float v = fmaxf(acc + hpb1[h], 0.f);
    g_hph[tb * 128 + h] = v;
    sr[h] = v * v;
    __syncthreads();
    for (int s2 = 64; s2 > 0; s2 >>= 1) {
        if (h < s2) sr[h] += sr[h + s2];
        __syncthreads();
    }
    if (h == 0) g_hphn[tb] = sqrtf(sr[0]);
}

// ============ Kernel C: categorical via bits-argmax + compacted candidates =
__global__ __launch_bounds__(256, 2) void k_samp(const float* __restrict__ w2,
                                                 const float* __restrict__ b2,
                                                 float* __restrict__ out) {
    __shared__ unsigned sm[4096];          // raw threefry bits
    __shared__ unsigned short slist[4096]; // candidate indices (compacted)
    __shared__ __align__(16) float shph[128];
    __shared__ float rs[256];
    __shared__ int ri[256];
    __shared__ unsigned s_wm[8];
    __shared__ int s_cnt;
    int row = blockIdx.x;                 // ((s*60)+t)*512 + b
    int b = row & 511;
    int q = row >> 9;
    int t = q % 60, s = q / 60;
    int tid = threadIdx.x;
    if (tid == 0) s_cnt = 0;
    if (tid < 128) shph[tid] = g_hph[(t * 512 + b) * 128 + tid];
    // -------- phase 1: bulk threefry, raw-bit row max --------
    unsigned base = (unsigned)row << 12;  // row*4096 fits u32
    unsigned mymax = 0;
#pragma unroll 4
    for (int i = tid; i < 4096; i += 256) {
        unsigned v = tf_fold<KS.a, KS.b>(base + (unsigned)i);
        sm[i] = v;
        mymax = max(mymax, v);
    }
    unsigned wm = __reduce_max_sync(0xffffffffu, mymax);
    if ((tid & 31) == 0) s_wm[tid >> 5] = wm;
    __syncthreads();
    // -------- phase 2a: conservative f32 threshold (all threads, no serialization)
    unsigned M = s_wm[0];
#pragma unroll
    for (int j = 1; j < 8; ++j) M = max(M, s_wm[j]);
    unsigned Bth;
    {
        float u01M = __uint_as_float(0x3f800000u | (M >> 9)) - 1.0f;
        float UM = u01M + TINYF;
        float l1 = __logf(UM);                       // < 0 always (mantissa < 2^23)
        float gM = -__logf(-l1);
        float delta = 2.0f * g_hphn[t * 512 + b] * g_cmax + g_brange
                    + 0.15f + 1e-3f * fabsf(gM);
        float gth = gM - delta;
        float uth = __expf(-__expf(-gth));
        int mth = (int)floorf(uth * 8388608.0f) - 64; // wide slack for fast-math err
        Bth = (mth > 0) ? ((unsigned)mth << 9) : 0u;
    }
    // compact candidates into slist
#pragma unroll 4
    for (int i = tid; i < 4096; i += 256) {
        if (sm[i] >= Bth) {
            int p = atomicAdd(&s_cnt, 1);
            slist[p] = (unsigned short)i;
        }
    }
    __syncthreads();
    int cnt = s_cnt;
    // -------- phase 2b: dense parallel exact scoring of candidates --------
    float best = -1e30f;
    int bi = 2147483647;
    for (int k = tid; k < cnt; k += 256) {
        int i = slist[k];
        unsigned m = sm[i] >> 9;
        float u01 = __uint_as_float(0x3f800000u | m) - 1.0f;
        float U = __fadd_rn(u01, TINYF);
        float l1 = (float)log((double)U);          // f32-accurate, fast-math-proof
        float g = -(float)log((double)(-l1));
        const float4* wv = (const float4*)(w2 + i * 128);
        float acc = 0.f;
#pragma unroll 8
        for (int kk = 0; kk < 32; ++kk) {
            float4 a = ((const float4*)shph)[kk];
            float4 c = wv[kk];
            acc = fmaf(a.x, c.x, acc); acc = fmaf(a.y, c.y, acc);
            acc = fmaf(a.z, c.z, acc); acc = fmaf(a.w, c.w, acc);
        }
        float score = __fadd_rn(g, acc + b2[i]);
        if (score > best || (score == best && i < bi)) { best = score; bi = i; }
    }
    rs[tid] = best; ri[tid] = bi;
    __syncthreads();
    for (int s2 = 128; s2 > 0; s2 >>= 1) {
        if (tid < s2) {
            float o = rs[tid + s2]; int oi = ri[tid + s2];
            if (o > rs[tid] || (o == rs[tid] && oi < ri[tid])) { rs[tid] = o; ri[tid] = oi; }
        }
        __syncthreads();
    }
    if (tid == 0) {
        int idx = ri[0];
        float px = -50.0f + (float)(idx & 63) * 1.5625f + 0.78125f;
        float py = -50.0f + (float)(idx >> 6) * 1.5625f + 0.78125f;
        int o = b * 720 + (1 + s) * 120 + t * 2;
        out[o] = px;
        out[o + 1] = py;
    }
}

// =========================== launch ========================================
extern "C" void kernel_launch(void* const* d_in, const int* in_sizes, int n_in,
                              void* d_out, int out_size) {
    const float* x    = (const float*)d_in[0];
    const float* hid  = (const float*)d_in[1];
    const float* wih0 = (const float*)d_in[3];
    const float* whh0 = (const float*)d_in[4];
    const float* bih0 = (const float*)d_in[5];
    const float* bhh0 = (const float*)d_in[6];
    const float* wih1 = (const float*)d_in[7];
    const float* whh1 = (const float*)d_in[8];
    const float* bih1 = (const float*)d_in[9];
    const float* bhh1 = (const float*)d_in[10];
    const float* hgw1 = (const float*)d_in[11];
    const float* hgb1 = (const float*)d_in[12];
    const float* hgw2 = (const float*)d_in[13];
    const float* hgb2 = (const float*)d_in[14];
    const float* hgw3 = (const float*)d_in[15];
    const float* hgb3 = (const float*)d_in[16];
    const float* cfw1 = (const float*)d_in[17];
    const float* cfb1 = (const float*)d_in[18];
    const float* cfw2 = (const float*)d_in[19];
    const float* cfb2 = (const float*)d_in[20];
    const float* hpw1 = (const float*)d_in[21];
    const float* hpb1 = (const float*)d_in[22];
    const float* hpw2 = (const float*)d_in[23];
    const float* hpb2 = (const float*)d_in[24];
    float* out = (float*)d_out;

    k_head<<<512, 128>>>(x, hid, wih0, whh0, bih0, bhh0, wih1, whh1, bih1, bhh1,
                         hgw1, hgb1, hgw2, hgb2, hgw3, hgb3,
                         cfw1, cfb1, cfw2, cfb2, out);
    k_w2<<<1, 512>>>(hpw2, hpb2);
    k_hph<<<60 * 512, 128>>>(hpw1, hpb1);
    k_samp<<<5 * 60 * 512, 256>>>(hpw2, hpb2, out);
}